// round 13
// baseline (speedup 1.0000x reference)
#include <cuda_runtime.h>
#include <cuda_fp16.h>
#include <cstdint>

// ============================================================================
// shift_Windows == 4 batched GEMMs:  Out[o,p] = sum_k W[o,k] * X[k,p] + bias[o]
//   per (b in {0,1}, g in {0,1}):  M(o)=1024, N(p)=13824, K=1024
//   X[k=s'*32+c', p] = x[b, c', t', p],  t' = (g*32 + s' - 16) & 63
//   Out row o=s*32+c  -> out[b, c, t, p], t = (g*32 + s - 16) & 63  (same map)
//
// Baseline compute_103 target: mma.sync.m16n8k16 + cp.async + ldmatrix.
// R12 = R10 mainloop (best: GEMM 281us, tensor 68%) made PERSISTENT:
//   - grid = 296 CTAs (2/SM, all resident); each CTA walks tiles bid+296*i
//     with one continuous global chunk counter; the 3-stage cp.async pipeline
//     never drains across tile boundaries (next tile's first chunks prefetch
//     under the current tile's last chunks + epilogue).
//   - kills wave transitions and per-tile cold prologue refills.
//   - R11's improved 2xfloat4 fused prepass kept; krev dropped (regressed).
// ============================================================================

#define HP3        13824     // 24^3 spatial positions per (b, t)
#define CH_STRIDE  884736    // 64*13824  (channel stride in x/out, elements)
#define B_STRIDE   28311552  // 32*884736 (batch stride, elements)

#define M_TILE 128           // o rows per CTA tile
#define N_TILE 128           // p cols per CTA tile
#define NUM_TILES 3456       // 8 * 108 * 4
#define GRID_CTAS 296        // 148 SMs * 2 resident CTAs

#define STAGE_BYTES 32768    // A 16KB + B 16KB
#define OFF_B_IN_STAGE 16384
#define SMEM_BYTES (3 * STAGE_BYTES)   // 96KB; 2 CTAs = 192KB <= 227KB

__device__ __half d_Wh[1024 * 1024];      // fp16 W
__device__ __half d_Xh[56623104];         // fp16 x  (2*32*96^3)

// ---------------- helpers ----------------
__device__ __forceinline__ uint32_t smem_to_u32(const void* p) {
    uint32_t a;
    asm("{ .reg .u64 t; cvta.to.shared.u64 t, %1; cvt.u32.u64 %0, t; }"
        : "=r"(a) : "l"(p));
    return a;
}
#define CP_ASYNC16(dst, src) \
    asm volatile("cp.async.cg.shared.global [%0], [%1], 16;" :: "r"(dst), "l"(src))
#define CP_COMMIT() asm volatile("cp.async.commit_group;" ::: "memory")
#define CP_WAIT(n)  asm volatile("cp.async.wait_group %0;" :: "n"(n) : "memory")

#define LDMATRIX_X4(r0, r1, r2, r3, addr) \
    asm volatile("ldmatrix.sync.aligned.m8n8.x4.shared.b16 {%0,%1,%2,%3}, [%4];" \
                 : "=r"(r0), "=r"(r1), "=r"(r2), "=r"(r3) : "r"(addr))
#define LDMATRIX_X4_T(r0, r1, r2, r3, addr) \
    asm volatile("ldmatrix.sync.aligned.m8n8.x4.trans.shared.b16 {%0,%1,%2,%3}, [%4];" \
                 : "=r"(r0), "=r"(r1), "=r"(r2), "=r"(r3) : "r"(addr))

#define MMA16816(d, a0, a1, a2, a3, b0, b1) \
    asm volatile("mma.sync.aligned.m16n8k16.row.col.f32.f16.f16.f32 " \
                 "{%0,%1,%2,%3}, {%4,%5,%6,%7}, {%8,%9}, {%0,%1,%2,%3};" \
                 : "+f"((d)[0]), "+f"((d)[1]), "+f"((d)[2]), "+f"((d)[3]) \
                 : "r"(a0), "r"(a1), "r"(a2), "r"(a3), "r"(b0), "r"(b1))

// ---------------- fused prepass: W and X fp32 -> fp16 (one launch) ----------
// 2 float4 per thread. blocks [0,512): W (262144 f4); [512, 512+27648): X.
__global__ void __launch_bounds__(256) conv_kernel(const float* __restrict__ W,
                                                   const float* __restrict__ x) {
    const float4* src;
    uint2* dst;
    int i;
    if (blockIdx.x < 512) {
        i = blockIdx.x * 512 + threadIdx.x;
        src = (const float4*)W; dst = (uint2*)d_Wh;
    } else {
        i = (blockIdx.x - 512) * 512 + threadIdx.x;
        src = (const float4*)x; dst = (uint2*)d_Xh;
    }
    float4 v0 = src[i];
    float4 v1 = src[i + 256];
    __half2 a0 = __float22half2_rn(make_float2(v0.x, v0.y));
    __half2 c0 = __float22half2_rn(make_float2(v0.z, v0.w));
    __half2 a1 = __float22half2_rn(make_float2(v1.x, v1.y));
    __half2 c1 = __float22half2_rn(make_float2(v1.z, v1.w));
    uint2 u0, u1;
    u0.x = *reinterpret_cast<const uint32_t*>(&a0);
    u0.y = *reinterpret_cast<const uint32_t*>(&c0);
    u1.x = *reinterpret_cast<const uint32_t*>(&a1);
    u1.y = *reinterpret_cast<const uint32_t*>(&c1);
    dst[i] = u0;
    dst[i + 256] = u1;
}

// ---------------- main GEMM (persistent) ----------------
__global__ void __launch_bounds__(256, 2)
swin_gemm_kernel(const float* __restrict__ bias, float* __restrict__ out) {
    extern __shared__ char sm[];
    const uint32_t smb = smem_to_u32(sm);
    const int tid  = threadIdx.x;
    const int lane = tid & 31;
    const int warp = tid >> 5;          // 0..7
    const int warp_m = warp & 3;        // o sub-tile (32 rows)
    const int warp_n = warp >> 2;       // p sub-tile (64 cols)
    const int bid = blockIdx.x;

    const int ntiles = (NUM_TILES - bid + GRID_CTAS - 1) / GRID_CTAS;
    const int end = ntiles * 16;        // total chunks for this CTA

    // tile id for global chunk cc (this CTA's sequence: bid + 296*i)
    auto tile_of = [&](int cc) -> int { return bid + (cc >> 4) * GRID_CTAS; };

    // ---- tile loaders (cp.async, both fp16, contiguous 16B chunks) ----
    auto load_tiles = [&](int stage, int cc) {
        const int t  = tile_of(cc);
        const int kc = cc & 15;
        const int o_base = (t & 7) * M_TILE;
        const int r  = t >> 3;
        const int bz = r / 108;
        const int p_base = (r - bz * 108) * N_TILE;
        const int b  = bz >> 1;
        const int g  = bz & 1;
        // A = W[o_base..+128][kc*64..+64], rows 128B, swizzled  (1024 chunks)
        uint32_t abase = smb + stage * STAGE_BYTES;
        #pragma unroll
        for (int i = 0; i < 4; i++) {
            int cid = tid + i * 256;
            int o = cid >> 3, c16 = cid & 7;
            const __half* src = d_Wh + (size_t)(o_base + o) * 1024 + kc * 64 + c16 * 8;
            uint32_t dst = abase + o * 128 + ((c16 * 16) ^ ((o & 7) << 4));
            CP_ASYNC16(dst, src);
        }
        // B = X[kc*64..+64][p_base..+128], rows 256B, swizzled by (k&7)  (1024 chunks)
        uint32_t bbase = abase + OFF_B_IN_STAGE;
        #pragma unroll
        for (int i = 0; i < 4; i++) {
            int cid = tid + i * 256;
            int kk = cid >> 4, c16 = cid & 15;
            int kg = kc * 64 + kk;
            int sp = kg >> 5, cp = kg & 31;
            int tp = ((g << 5) + sp - 16) & 63;
            const __half* src = d_Xh + (size_t)b * B_STRIDE + (size_t)cp * CH_STRIDE
                              + tp * HP3 + p_base + c16 * 8;
            uint32_t dst = bbase + kk * 256 + ((c16 * 16) ^ ((kk & 7) << 4));
            CP_ASYNC16(dst, src);
        }
    };

    float acc[2][8][4];
    #pragma unroll
    for (int mi = 0; mi < 2; mi++)
        #pragma unroll
        for (int ni = 0; ni < 8; ni++)
            #pragma unroll
            for (int r = 0; r < 4; r++) acc[mi][ni][r] = 0.f;

    load_tiles(0, 0); CP_COMMIT();
    load_tiles(1, 1); CP_COMMIT();

    #pragma unroll 1
    for (int cc = 0; cc < end; cc++) {
        const int stage = cc % 3;
        if (cc < end - 1) { CP_WAIT(1); } else { CP_WAIT(0); }
        __syncthreads();   // stage[cc] visible to all; stage (cc+2)%3 free
        if (cc + 2 < end) {
            load_tiles((cc + 2) % 3, cc + 2);
            CP_COMMIT();
        }

        const uint32_t abase = smb + stage * STAGE_BYTES;
        const uint32_t bbase = abase + OFF_B_IN_STAGE;
        #pragma unroll
        for (int k16 = 0; k16 < 4; k16++) {
            uint32_t a[2][4], bb[4][4];
            #pragma unroll
            for (int mi = 0; mi < 2; mi++) {
                int row = warp_m * 32 + mi * 16 + (lane & 15);
                int col = k16 * 32 + (lane >> 4) * 16;
                uint32_t addr = abase + row * 128 + (col ^ ((row & 7) << 4));
                LDMATRIX_X4(a[mi][0], a[mi][1], a[mi][2], a[mi][3], addr);
            }
            #pragma unroll
            for (int ni = 0; ni < 4; ni++) {
                int row = k16 * 16 + (lane & 15);
                int col = warp_n * 128 + ni * 32 + (lane >> 4) * 16;   // bytes
                uint32_t addr = bbase + row * 256 + (col ^ ((row & 7) << 4));
                LDMATRIX_X4_T(bb[ni][0], bb[ni][1], bb[ni][2], bb[ni][3], addr);
            }
            #pragma unroll
            for (int mi = 0; mi < 2; mi++)
                #pragma unroll
                for (int ni = 0; ni < 4; ni++) {
                    MMA16816(acc[mi][2 * ni],     a[mi][0], a[mi][1], a[mi][2], a[mi][3],
                             bb[ni][0], bb[ni][1]);
                    MMA16816(acc[mi][2 * ni + 1], a[mi][0], a[mi][1], a[mi][2], a[mi][3],
                             bb[ni][2], bb[ni][3]);
                }
        }

        // ---- tile finished? epilogue + acc reset (no smem use: overlaps loads)
        if ((cc & 15) == 15) {
            const int t  = tile_of(cc);
            const int o_base = (t & 7) * M_TILE;
            const int r  = t >> 3;
            const int bz = r / 108;
            const int p_base = (r - bz * 108) * N_TILE;
            const int b  = bz >> 1;
            const int g  = bz & 1;
            #pragma unroll
            for (int mi = 0; mi < 2; mi++) {
                #pragma unroll
                for (int rr = 0; rr < 2; rr++) {
                    int o = o_base + warp_m * 32 + mi * 16 + rr * 8 + (lane >> 2);
                    int s = o >> 5, c = o & 31;
                    int tt = ((g << 5) + s - 16) & 63;
                    float bv = __ldg(&bias[o]);
                    float* orow = out + (size_t)b * B_STRIDE + (size_t)c * CH_STRIDE
                                + tt * HP3 + p_base + warp_n * 64 + 2 * (lane & 3);
                    #pragma unroll
                    for (int ni = 0; ni < 8; ni++) {
                        float2 v;
                        v.x = acc[mi][ni][rr * 2 + 0] + bv;
                        v.y = acc[mi][ni][rr * 2 + 1] + bv;
                        __stcs(reinterpret_cast<float2*>(orow + ni * 8), v);
                        acc[mi][ni][rr * 2 + 0] = 0.f;
                        acc[mi][ni][rr * 2 + 1] = 0.f;
                    }
                }
            }
        }
    }
}

// ---------------- launch ----------------
extern "C" void kernel_launch(void* const* d_in, const int* in_sizes, int n_in,
                              void* d_out, int out_size) {
    const float* x    = (const float*)d_in[0];   // (2,32,96,96,96) fp32
    const float* W    = (const float*)d_in[1];   // (1024,1024) fp32
    const float* bias = (const float*)d_in[2];   // (1024,) fp32
    float* out = (float*)d_out;

    cudaFuncSetAttribute(swin_gemm_kernel,
                         cudaFuncAttributeMaxDynamicSharedMemorySize, SMEM_BYTES);

    conv_kernel<<<512 + 27648, 256>>>(W, x);     // fused W+X fp32->fp16, 2 f4/thread

    swin_gemm_kernel<<<GRID_CTAS, 256, SMEM_BYTES>>>(bias, out);
}

// round 14
// speedup vs baseline: 1.0612x; 1.0612x over previous
#include <cuda_runtime.h>
#include <cuda_fp16.h>
#include <cstdint>

// ============================================================================
// shift_Windows == 4 batched GEMMs:  Out[o,p] = sum_k W[o,k] * X[k,p] + bias[o]
//   per (b in {0,1}, g in {0,1}):  M(o)=1024, N(p)=13824, K=1024
//   X[k=s'*32+c', p] = x[b, c', t', p],  t' = (g*32 + s' - 16) & 63
//   Out row o=s*32+c  -> out[b, c, t, p], t = (g*32 + s - 16) & 63  (same map)
//
// Baseline compute_103 target: mma.sync.m16n8k16 + cp.async + ldmatrix.
// R13 = the two best measured halves, recombined unmodified:
//   - GEMM: R10 mainloop exactly (281us measured, tensor 68.4%): 128x128 CTA,
//     256 thr, warp 32x64, both operands fp16 via cp.async, 3-stage pipeline,
//     ONE __syncthreads per K-chunk, streaming epilogue stores. (krev removed,
//     persistence removed — both measured as regressions.)
//   - Prepass: R11's fused W+X fp32->fp16, 2 float4/thread (49us, DRAM-bound).
// ============================================================================

#define HP3        13824     // 24^3 spatial positions per (b, t)
#define CH_STRIDE  884736    // 64*13824  (channel stride in x/out, elements)
#define B_STRIDE   28311552  // 32*884736 (batch stride, elements)

#define M_TILE 128           // o rows per CTA
#define N_TILE 128           // p cols per CTA
#define N_CHUNKS 16          // 1024 / 64

#define STAGE_BYTES 32768    // A 16KB + B 16KB
#define OFF_B_IN_STAGE 16384
#define SMEM_BYTES (3 * STAGE_BYTES)   // 96KB; 2 CTAs = 192KB <= 227KB

__device__ __half d_Wh[1024 * 1024];      // fp16 W
__device__ __half d_Xh[56623104];         // fp16 x  (2*32*96^3)

// ---------------- helpers ----------------
__device__ __forceinline__ uint32_t smem_to_u32(const void* p) {
    uint32_t a;
    asm("{ .reg .u64 t; cvta.to.shared.u64 t, %1; cvt.u32.u64 %0, t; }"
        : "=r"(a) : "l"(p));
    return a;
}
#define CP_ASYNC16(dst, src) \
    asm volatile("cp.async.cg.shared.global [%0], [%1], 16;" :: "r"(dst), "l"(src))
#define CP_COMMIT() asm volatile("cp.async.commit_group;" ::: "memory")
#define CP_WAIT(n)  asm volatile("cp.async.wait_group %0;" :: "n"(n) : "memory")

#define LDMATRIX_X4(r0, r1, r2, r3, addr) \
    asm volatile("ldmatrix.sync.aligned.m8n8.x4.shared.b16 {%0,%1,%2,%3}, [%4];" \
                 : "=r"(r0), "=r"(r1), "=r"(r2), "=r"(r3) : "r"(addr))
#define LDMATRIX_X4_T(r0, r1, r2, r3, addr) \
    asm volatile("ldmatrix.sync.aligned.m8n8.x4.trans.shared.b16 {%0,%1,%2,%3}, [%4];" \
                 : "=r"(r0), "=r"(r1), "=r"(r2), "=r"(r3) : "r"(addr))

#define MMA16816(d, a0, a1, a2, a3, b0, b1) \
    asm volatile("mma.sync.aligned.m16n8k16.row.col.f32.f16.f16.f32 " \
                 "{%0,%1,%2,%3}, {%4,%5,%6,%7}, {%8,%9}, {%0,%1,%2,%3};" \
                 : "+f"((d)[0]), "+f"((d)[1]), "+f"((d)[2]), "+f"((d)[3]) \
                 : "r"(a0), "r"(a1), "r"(a2), "r"(a3), "r"(b0), "r"(b1))

// ---------------- fused prepass: W and X fp32 -> fp16 (one launch) ----------
// 2 float4 per thread. blocks [0,512): W (262144 f4); [512, 512+27648): X.
__global__ void __launch_bounds__(256) conv_kernel(const float* __restrict__ W,
                                                   const float* __restrict__ x) {
    const float4* src;
    uint2* dst;
    int i;
    if (blockIdx.x < 512) {
        i = blockIdx.x * 512 + threadIdx.x;
        src = (const float4*)W; dst = (uint2*)d_Wh;
    } else {
        i = (blockIdx.x - 512) * 512 + threadIdx.x;
        src = (const float4*)x; dst = (uint2*)d_Xh;
    }
    float4 v0 = src[i];
    float4 v1 = src[i + 256];
    __half2 a0 = __float22half2_rn(make_float2(v0.x, v0.y));
    __half2 c0 = __float22half2_rn(make_float2(v0.z, v0.w));
    __half2 a1 = __float22half2_rn(make_float2(v1.x, v1.y));
    __half2 c1 = __float22half2_rn(make_float2(v1.z, v1.w));
    uint2 u0, u1;
    u0.x = *reinterpret_cast<const uint32_t*>(&a0);
    u0.y = *reinterpret_cast<const uint32_t*>(&c0);
    u1.x = *reinterpret_cast<const uint32_t*>(&a1);
    u1.y = *reinterpret_cast<const uint32_t*>(&c1);
    dst[i] = u0;
    dst[i + 256] = u1;
}

// ---------------- main GEMM ----------------
__global__ void __launch_bounds__(256, 2)
swin_gemm_kernel(const float* __restrict__ bias, float* __restrict__ out) {
    extern __shared__ char sm[];
    const uint32_t smb = smem_to_u32(sm);
    const int tid  = threadIdx.x;
    const int lane = tid & 31;
    const int warp = tid >> 5;          // 0..7
    const int warp_m = warp & 3;        // o sub-tile (32 rows)
    const int warp_n = warp >> 2;       // p sub-tile (64 cols)

    const int o_base = blockIdx.x * M_TILE;
    const int p_base = blockIdx.y * N_TILE;
    const int bg = blockIdx.z;
    const int b  = bg >> 1;
    const int g  = bg & 1;

    float acc[2][8][4];
    #pragma unroll
    for (int mi = 0; mi < 2; mi++)
        #pragma unroll
        for (int ni = 0; ni < 8; ni++)
            #pragma unroll
            for (int r = 0; r < 4; r++) acc[mi][ni][r] = 0.f;

    // ---- tile loaders (cp.async, both fp16, contiguous 16B chunks) ----
    auto load_tiles = [&](int stage, int kc) {
        // A = W[o_base..+128][kc*64..+64], rows 128B, swizzled  (1024 chunks)
        uint32_t abase = smb + stage * STAGE_BYTES;
        #pragma unroll
        for (int i = 0; i < 4; i++) {
            int cid = tid + i * 256;
            int o = cid >> 3, c16 = cid & 7;
            const __half* src = d_Wh + (size_t)(o_base + o) * 1024 + kc * 64 + c16 * 8;
            uint32_t dst = abase + o * 128 + ((c16 * 16) ^ ((o & 7) << 4));
            CP_ASYNC16(dst, src);
        }
        // B = X[kc*64..+64][p_base..+128], rows 256B, swizzled by (k&7)  (1024 chunks)
        uint32_t bbase = abase + OFF_B_IN_STAGE;
        #pragma unroll
        for (int i = 0; i < 4; i++) {
            int cid = tid + i * 256;
            int kk = cid >> 4, c16 = cid & 15;
            int kg = kc * 64 + kk;
            int sp = kg >> 5, cp = kg & 31;
            int tp = ((g << 5) + sp - 16) & 63;
            const __half* src = d_Xh + (size_t)b * B_STRIDE + (size_t)cp * CH_STRIDE
                              + tp * HP3 + p_base + c16 * 8;
            uint32_t dst = bbase + kk * 256 + ((c16 * 16) ^ ((kk & 7) << 4));
            CP_ASYNC16(dst, src);
        }
    };

    load_tiles(0, 0); CP_COMMIT();
    load_tiles(1, 1); CP_COMMIT();

    #pragma unroll 1
    for (int kc = 0; kc < N_CHUNKS; kc++) {
        const int stage = kc % 3;
        if (kc < N_CHUNKS - 1) { CP_WAIT(1); } else { CP_WAIT(0); }
        __syncthreads();   // stage[kc] data visible to all; stage (kc+2)%3 free
        if (kc + 2 < N_CHUNKS) {
            load_tiles((kc + 2) % 3, kc + 2);
            CP_COMMIT();
        }

        const uint32_t abase = smb + stage * STAGE_BYTES;
        const uint32_t bbase = abase + OFF_B_IN_STAGE;
        #pragma unroll
        for (int k16 = 0; k16 < 4; k16++) {
            uint32_t a[2][4], bb[4][4];
            #pragma unroll
            for (int mi = 0; mi < 2; mi++) {
                int row = warp_m * 32 + mi * 16 + (lane & 15);
                int col = k16 * 32 + (lane >> 4) * 16;
                uint32_t addr = abase + row * 128 + (col ^ ((row & 7) << 4));
                LDMATRIX_X4(a[mi][0], a[mi][1], a[mi][2], a[mi][3], addr);
            }
            #pragma unroll
            for (int ni = 0; ni < 4; ni++) {
                int row = k16 * 16 + (lane & 15);
                int col = warp_n * 128 + ni * 32 + (lane >> 4) * 16;   // bytes
                uint32_t addr = bbase + row * 256 + (col ^ ((row & 7) << 4));
                LDMATRIX_X4_T(bb[ni][0], bb[ni][1], bb[ni][2], bb[ni][3], addr);
            }
            #pragma unroll
            for (int mi = 0; mi < 2; mi++)
                #pragma unroll
                for (int ni = 0; ni < 4; ni++) {
                    MMA16816(acc[mi][2 * ni],     a[mi][0], a[mi][1], a[mi][2], a[mi][3],
                             bb[ni][0], bb[ni][1]);
                    MMA16816(acc[mi][2 * ni + 1], a[mi][0], a[mi][1], a[mi][2], a[mi][3],
                             bb[ni][2], bb[ni][3]);
                }
        }
    }

    // ---- epilogue: D[m=o, n=p] + bias[o] -> out[b, c, t, ...], streaming stores
    #pragma unroll
    for (int mi = 0; mi < 2; mi++) {
        #pragma unroll
        for (int rr = 0; rr < 2; rr++) {
            int o = o_base + warp_m * 32 + mi * 16 + rr * 8 + (lane >> 2);
            int s = o >> 5, c = o & 31;
            int t = ((g << 5) + s - 16) & 63;
            float bv = __ldg(&bias[o]);
            float* orow = out + (size_t)b * B_STRIDE + (size_t)c * CH_STRIDE
                        + t * HP3 + p_base + warp_n * 64 + 2 * (lane & 3);
            #pragma unroll
            for (int ni = 0; ni < 8; ni++) {
                float2 v;
                v.x = acc[mi][ni][rr * 2 + 0] + bv;
                v.y = acc[mi][ni][rr * 2 + 1] + bv;
                __stcs(reinterpret_cast<float2*>(orow + ni * 8), v);
            }
        }
    }
}

// ---------------- launch ----------------
extern "C" void kernel_launch(void* const* d_in, const int* in_sizes, int n_in,
                              void* d_out, int out_size) {
    const float* x    = (const float*)d_in[0];   // (2,32,96,96,96) fp32
    const float* W    = (const float*)d_in[1];   // (1024,1024) fp32
    const float* bias = (const float*)d_in[2];   // (1024,) fp32
    float* out = (float*)d_out;

    cudaFuncSetAttribute(swin_gemm_kernel,
                         cudaFuncAttributeMaxDynamicSharedMemorySize, SMEM_BYTES);

    conv_kernel<<<512 + 27648, 256>>>(W, x);     // fused W+X fp32->fp16, 2 f4/thread

    dim3 grid(1024 / M_TILE, HP3 / N_TILE, 4);   // (8, 108, 4); x fastest -> X L2 reuse
    swin_gemm_kernel<<<grid, 256, SMEM_BYTES>>>(bias, out);
}